// round 1
// baseline (speedup 1.0000x reference)
#include <cuda_runtime.h>
#include <math.h>

// ---------------- problem constants ----------------
#define Bv   16
#define Sv   256
#define Tv   2048
#define Dv   512
#define Hv   8
#define DHv  64
#define Lv   6
#define FFv  2048
#define NMv  80
#define NTOK (Bv*Sv)            // 4096 tokens

// ---------------- scratch (no allocs allowed) ----------------
__device__ float g_x   [NTOK*Dv];
__device__ float g_qkv [NTOK*3*Dv];
__device__ float g_attn[NTOK*Dv];
__device__ float g_tmp [NTOK*Dv];
__device__ float g_big [NTOK*FFv];     // ff1 / mel hidden (reused)
__device__ float g_durh[NTOK*256];
__device__ float g_mels[NTOK*NMv];
__device__ float g_inv [NMv];
__device__ int   g_cum [Bv*Sv];
__device__ int   g_idx [Bv*Tv];

// ---------------- helpers ----------------
__device__ __forceinline__ float blk_sum(float v, float* sbuf) {
    __syncthreads();
    int lane = threadIdx.x & 31, w = threadIdx.x >> 5;
    #pragma unroll
    for (int o = 16; o; o >>= 1) v += __shfl_xor_sync(0xffffffffu, v, o);
    if (lane == 0) sbuf[w] = v;
    __syncthreads();
    int nw = blockDim.x >> 5;
    float r = (threadIdx.x < nw) ? sbuf[threadIdx.x] : 0.f;
    if (w == 0) {
        #pragma unroll
        for (int o = 16; o; o >>= 1) r += __shfl_xor_sync(0xffffffffu, r, o);
        if (lane == 0) sbuf[0] = r;
    }
    __syncthreads();
    return sbuf[0];
}

// ---------------- SGEMM: C[M,N] = A[M,K] @ B[K,N] (+bias)(+relu) ----------------
// EPI: 0 = none, 1 = bias, 2 = bias+relu
// Requires: M % 64 == 0, K % 16 == 0. N arbitrary (guarded).
template<int EPI>
__global__ void __launch_bounds__(256)
sgemm_k(const float* __restrict__ A, const float* __restrict__ B,
        const float* __restrict__ bias, float* __restrict__ C,
        int M, int N, int K)
{
    const int BK = 16;
    __shared__ float As[BK][64];
    __shared__ float Bs[BK][64];
    int tid = threadIdx.x;
    int m0 = blockIdx.y * 64, n0 = blockIdx.x * 64;
    int tx = tid & 15, ty = tid >> 4;           // 16 x 16 thread grid, 4x4 each
    int arow = tid >> 2, ak = (tid & 3) * 4;    // A tile: 64 rows x 16 k
    int brow = tid >> 4, bcol = (tid & 15) * 4; // B tile: 16 rows x 64 n

    float acc[4][4] = {};

    for (int k0 = 0; k0 < K; k0 += BK) {
        // load A tile (transposed into smem)
        float4 av = *(const float4*)(A + (size_t)(m0 + arow) * K + k0 + ak);
        As[ak+0][arow] = av.x; As[ak+1][arow] = av.y;
        As[ak+2][arow] = av.z; As[ak+3][arow] = av.w;
        // load B tile (N-guarded)
        int gc = n0 + bcol;
        float4 bv;
        const float* Brow = B + (size_t)(k0 + brow) * N;
        if (gc + 3 < N) {
            bv = *(const float4*)(Brow + gc);
        } else {
            bv.x = (gc+0 < N) ? Brow[gc+0] : 0.f;
            bv.y = (gc+1 < N) ? Brow[gc+1] : 0.f;
            bv.z = (gc+2 < N) ? Brow[gc+2] : 0.f;
            bv.w = (gc+3 < N) ? Brow[gc+3] : 0.f;
        }
        *(float4*)&Bs[brow][bcol] = bv;
        __syncthreads();

        #pragma unroll
        for (int kk = 0; kk < BK; kk++) {
            float4 a = *(const float4*)&As[kk][ty * 4];
            float4 b = *(const float4*)&Bs[kk][tx * 4];
            float ar[4] = {a.x, a.y, a.z, a.w};
            float br[4] = {b.x, b.y, b.z, b.w};
            #pragma unroll
            for (int i = 0; i < 4; i++)
                #pragma unroll
                for (int j = 0; j < 4; j++)
                    acc[i][j] += ar[i] * br[j];
        }
        __syncthreads();
    }

    // epilogue
    int gc = n0 + tx * 4;
    float bb[4] = {0.f, 0.f, 0.f, 0.f};
    if (EPI >= 1) {
        #pragma unroll
        for (int j = 0; j < 4; j++) if (gc + j < N) bb[j] = bias[gc + j];
    }
    #pragma unroll
    for (int i = 0; i < 4; i++) {
        int gr = m0 + ty * 4 + i;
        float r[4];
        #pragma unroll
        for (int j = 0; j < 4; j++) {
            r[j] = acc[i][j] + bb[j];
            if (EPI == 2) r[j] = r[j] > 0.f ? r[j] : 0.f;
        }
        float* Crow = C + (size_t)gr * N;
        if (gc + 3 < N) {
            float4 o = make_float4(r[0], r[1], r[2], r[3]);
            *(float4*)(Crow + gc) = o;
        } else {
            #pragma unroll
            for (int j = 0; j < 4; j++) if (gc + j < N) Crow[gc + j] = r[j];
        }
    }
}

// ---------------- embedding + positional encoding ----------------
__global__ void __launch_bounds__(128)
embed_k(const int* __restrict__ ids, const float* __restrict__ emb,
        const float* __restrict__ pe, float* __restrict__ x)
{
    int token = blockIdx.x;
    int tid = threadIdx.x;
    int s = token % Sv;
    int id = ids[token];
    float4 e = ((const float4*)(emb + (size_t)id * Dv))[tid];
    float4 p = ((const float4*)(pe + (size_t)s * Dv))[tid];
    e.x += p.x; e.y += p.y; e.z += p.z; e.w += p.w;
    ((float4*)(x + (size_t)token * Dv))[tid] = e;
}

// ---------------- fused attention (one block per (b,h), online softmax) ------
__global__ void __launch_bounds__(256)
attn_k(const float* __restrict__ qkv, const int* __restrict__ lens,
       float* __restrict__ o)
{
    extern __shared__ float sh[];          // Ks[256*64] | Vs[256*64]
    float* Ks = sh;
    float* Vs = sh + Sv * DHv;
    int h = blockIdx.x, b = blockIdx.y;
    int t = threadIdx.x;                   // query row

    const float* base = qkv + (size_t)b * Sv * (3 * Dv);
    const float4* krow = (const float4*)(base + (size_t)t * 3 * Dv + Dv     + h * DHv);
    const float4* vrow = (const float4*)(base + (size_t)t * 3 * Dv + 2 * Dv + h * DHv);
    float4* ksd = (float4*)(Ks + t * DHv);
    float4* vsd = (float4*)(Vs + t * DHv);
    #pragma unroll
    for (int i = 0; i < 16; i++) { ksd[i] = krow[i]; vsd[i] = vrow[i]; }
    __syncthreads();

    int len = lens[b];
    float4 q4[16];
    const float4* qrow = (const float4*)(base + (size_t)t * 3 * Dv + h * DHv);
    #pragma unroll
    for (int i = 0; i < 16; i++) q4[i] = qrow[i];

    float4 a4[16];
    #pragma unroll
    for (int i = 0; i < 16; i++) a4[i] = make_float4(0.f, 0.f, 0.f, 0.f);

    const float scale = 0.125f;            // 1/sqrt(64)
    float m = -1e30f, l = 0.f;

    for (int j = 0; j < len; j++) {
        const float4* kj = (const float4*)(Ks + j * DHv);
        float s = 0.f;
        #pragma unroll
        for (int i = 0; i < 16; i++) {
            float4 kv = kj[i];
            s += q4[i].x * kv.x + q4[i].y * kv.y + q4[i].z * kv.z + q4[i].w * kv.w;
        }
        s *= scale;
        if (s > m) {                       // lazy max update (rare)
            float corr = expf(m - s);
            l *= corr;
            #pragma unroll
            for (int i = 0; i < 16; i++) {
                a4[i].x *= corr; a4[i].y *= corr; a4[i].z *= corr; a4[i].w *= corr;
            }
            m = s;
        }
        float e = expf(s - m);
        l += e;
        const float4* vj = (const float4*)(Vs + j * DHv);
        #pragma unroll
        for (int i = 0; i < 16; i++) {
            float4 vv = vj[i];
            a4[i].x += e * vv.x; a4[i].y += e * vv.y;
            a4[i].z += e * vv.z; a4[i].w += e * vv.w;
        }
    }

    float inv = (l > 0.f) ? 1.f / l : 0.f;
    float4* orow = (float4*)(o + ((size_t)b * Sv + t) * Dv + h * DHv);
    #pragma unroll
    for (int i = 0; i < 16; i++) {
        float4 r = a4[i];
        r.x *= inv; r.y *= inv; r.z *= inv; r.w *= inv;
        orow[i] = r;
    }
}

// ---------------- residual add + LayerNorm (in-place safe) ----------------
__global__ void __launch_bounds__(128)
add_ln_k(const float* __restrict__ x, const float* __restrict__ y,
         const float* __restrict__ s, const float* __restrict__ bta,
         float* __restrict__ out)
{
    __shared__ float sbuf[8];
    int row = blockIdx.x, tid = threadIdx.x;
    float4 v = ((const float4*)(x + (size_t)row * Dv))[tid];
    float4 w = ((const float4*)(y + (size_t)row * Dv))[tid];
    v.x += w.x; v.y += w.y; v.z += w.z; v.w += w.w;

    float sum = blk_sum(v.x + v.y + v.z + v.w, sbuf);
    float mean = sum * (1.f / Dv);
    float dx = v.x - mean, dy = v.y - mean, dz = v.z - mean, dw = v.w - mean;
    float var = blk_sum(dx*dx + dy*dy + dz*dz + dw*dw, sbuf) * (1.f / Dv);
    float rstd = rsqrtf(var + 1e-5f);

    float4 sv = ((const float4*)s)[tid];
    float4 bv = ((const float4*)bta)[tid];
    float4 r;
    r.x = dx * rstd * sv.x + bv.x;
    r.y = dy * rstd * sv.y + bv.y;
    r.z = dz * rstd * sv.z + bv.z;
    r.w = dw * rstd * sv.w + bv.w;
    ((float4*)(out + (size_t)row * Dv))[tid] = r;
}

// ---------------- duration head: softplus(durh @ W2 + b2) ----------------
__global__ void __launch_bounds__(256)
dur_head_k(const float* __restrict__ durh, const float* __restrict__ W2,
           const float* __restrict__ b2, float* __restrict__ dur)
{
    __shared__ float sbuf[8];
    int row = blockIdx.x, tid = threadIdx.x;
    float v = durh[(size_t)row * 256 + tid] * W2[tid];
    v = blk_sum(v, sbuf);
    if (tid == 0) {
        float z = v + b2[0];
        dur[row] = (z > 20.f) ? z : log1pf(expf(z));
    }
}

// ---------------- cumulative sum of clamped-rounded durations ----------------
__global__ void cumsum_k(const float* __restrict__ dur, int* __restrict__ cum)
{
    int b = blockIdx.x;
    if (threadIdx.x == 0) {
        int c = 0;
        for (int s2 = 0; s2 < Sv; s2++) {
            int d = (int)rintf(dur[b * Sv + s2]);   // round-half-even, matches jnp.round
            if (d < 1) d = 1;
            c += d;
            cum[b * Sv + s2] = c;
        }
    }
}

// ---------------- per-frame source index via binary search ----------------
__global__ void __launch_bounds__(256)
idx_k(const int* __restrict__ cum, int* __restrict__ idx)
{
    int b = blockIdx.y;
    int t = blockIdx.x * 256 + threadIdx.x;
    const int* c = cum + b * Sv;
    int total = c[Sv - 1];
    int lo = 0, hi = Sv;                   // count of c[s] <= t
    while (lo < hi) { int mid = (lo + hi) >> 1; if (c[mid] <= t) lo = mid + 1; else hi = mid; }
    int ix = lo > (Sv - 1) ? (Sv - 1) : lo;
    idx[b * Tv + t] = (t < total) ? ix : -1;
}

// ---------------- mel value for invalid frames: relu(b1) @ W2 + b2 ----------
__global__ void __launch_bounds__(256)
melinv_k(const float* __restrict__ b1, const float* __restrict__ W2,
         const float* __restrict__ b2, float* __restrict__ inv)
{
    __shared__ float sbuf[8];
    int nm = blockIdx.x, tid = threadIdx.x;
    float v = 0.f;
    for (int f = tid; f < FFv; f += 256) {
        float r = b1[f]; r = r > 0.f ? r : 0.f;
        v += r * W2[(size_t)f * NMv + nm];
    }
    v = blk_sum(v, sbuf);
    if (tid == 0) inv[nm] = v + b2[nm];
}

// ---------------- gather mel rows into [B, NM, T] ----------------
__global__ void __launch_bounds__(256)
gather_k(const int* __restrict__ idx, const float* __restrict__ mels,
         const float* __restrict__ inv, float* __restrict__ mel)
{
    int t = blockIdx.x * 256 + threadIdx.x;
    int bn = blockIdx.y;                   // b*NM + nm
    int b = bn / NMv, nm = bn % NMv;
    int iv = idx[b * Tv + t];
    mel[(size_t)bn * Tv + t] =
        (iv < 0) ? inv[nm] : mels[((size_t)b * Sv + iv) * NMv + nm];
}

// ---------------- host launcher ----------------
extern "C" void kernel_launch(void* const* d_in, const int* in_sizes, int n_in,
                              void* d_out, int out_size)
{
    const int*   ids    = (const int*)  d_in[0];
    const int*   lens   = (const int*)  d_in[1];
    // d_in[2] = mel_targets (only defines T, unused)
    const float* emb    = (const float*)d_in[3];
    const float* pe     = (const float*)d_in[4];
    const float* Wqkv   = (const float*)d_in[5];
    const float* bqkv   = (const float*)d_in[6];
    const float* Wo     = (const float*)d_in[7];
    const float* bo     = (const float*)d_in[8];
    const float* ln1s   = (const float*)d_in[9];
    const float* ln1b   = (const float*)d_in[10];
    const float* ln2s   = (const float*)d_in[11];
    const float* ln2b   = (const float*)d_in[12];
    const float* W1     = (const float*)d_in[13];
    const float* b1     = (const float*)d_in[14];
    const float* W2     = (const float*)d_in[15];
    const float* b2     = (const float*)d_in[16];
    const float* melW1  = (const float*)d_in[17];
    const float* melb1  = (const float*)d_in[18];
    const float* melW2  = (const float*)d_in[19];
    const float* melb2  = (const float*)d_in[20];
    const float* durW1  = (const float*)d_in[21];
    const float* durb1  = (const float*)d_in[22];
    const float* durW2  = (const float*)d_in[23];
    const float* durb2  = (const float*)d_in[24];

    float* out     = (float*)d_out;
    float* out_mel = out;                              // [B, NM, T]
    float* out_dur = out + (size_t)Bv * NMv * Tv;      // [B, S]
    float* out_enc = out_dur + (size_t)Bv * Sv;        // [B, S, D]

    float *x, *qkv, *attn, *tmp, *big, *durh, *mels, *inv;
    int *cum, *idxp;
    cudaGetSymbolAddress((void**)&x,    g_x);
    cudaGetSymbolAddress((void**)&qkv,  g_qkv);
    cudaGetSymbolAddress((void**)&attn, g_attn);
    cudaGetSymbolAddress((void**)&tmp,  g_tmp);
    cudaGetSymbolAddress((void**)&big,  g_big);
    cudaGetSymbolAddress((void**)&durh, g_durh);
    cudaGetSymbolAddress((void**)&mels, g_mels);
    cudaGetSymbolAddress((void**)&inv,  g_inv);
    cudaGetSymbolAddress((void**)&cum,  g_cum);
    cudaGetSymbolAddress((void**)&idxp, g_idx);

    const int attn_smem = 2 * Sv * DHv * (int)sizeof(float);   // 128 KB
    cudaFuncSetAttribute(attn_k, cudaFuncAttributeMaxDynamicSharedMemorySize, attn_smem);

    embed_k<<<NTOK, 128>>>(ids, emb, pe, x);

    for (int l = 0; l < Lv; l++) {
        const float* Wq = Wqkv + (size_t)l * Dv * 3 * Dv;
        sgemm_k<1><<<dim3(24, 64), 256>>>(x, Wq, bqkv + l * 3 * Dv, qkv, NTOK, 3 * Dv, Dv);
        attn_k<<<dim3(Hv, Bv), 256, attn_smem>>>(qkv, lens, attn);
        sgemm_k<1><<<dim3(8, 64), 256>>>(attn, Wo + (size_t)l * Dv * Dv, bo + l * Dv,
                                         tmp, NTOK, Dv, Dv);
        add_ln_k<<<NTOK, 128>>>(x, tmp, ln1s + l * Dv, ln1b + l * Dv, x);
        sgemm_k<2><<<dim3(32, 64), 256>>>(x, W1 + (size_t)l * Dv * FFv, b1 + l * FFv,
                                          big, NTOK, FFv, Dv);
        sgemm_k<1><<<dim3(8, 64), 256>>>(big, W2 + (size_t)l * FFv * Dv, b2 + l * Dv,
                                         tmp, NTOK, Dv, FFv);
        add_ln_k<<<NTOK, 128>>>(x, tmp, ln2s + l * Dv, ln2b + l * Dv, x);
    }

    // enc output
    cudaMemcpyAsync(out_enc, x, (size_t)NTOK * Dv * sizeof(float),
                    cudaMemcpyDeviceToDevice);

    // duration head
    sgemm_k<2><<<dim3(4, 64), 256>>>(x, durW1, durb1, durh, NTOK, 256, Dv);
    dur_head_k<<<NTOK, 256>>>(durh, durW2, durb2, out_dur);
    cumsum_k<<<Bv, 32>>>(out_dur, cum);

    // mel head on the S=256 source tokens (gather commutes with row-wise MLP)
    sgemm_k<2><<<dim3(32, 64), 256>>>(x, melW1, melb1, big, NTOK, FFv, Dv);
    sgemm_k<1><<<dim3(2, 64), 256>>>(big, melW2, melb2, mels, NTOK, NMv, FFv);
    melinv_k<<<NMv, 256>>>(melb1, melW2, melb2, inv);

    idx_k<<<dim3(Tv / 256, Bv), 256>>>(cum, idxp);
    gather_k<<<dim3(Tv / 256, Bv * NMv), 256>>>(idxp, mels, inv, out_mel);
}

// round 3
// speedup vs baseline: 2.2355x; 2.2355x over previous
#include <cuda_runtime.h>
#include <cuda_bf16.h>
#include <math.h>
#include <stdint.h>

// ---------------- problem constants ----------------
#define Bv   16
#define Sv   256
#define Tv   2048
#define Dv   512
#define Hv   8
#define DHv  64
#define Lv   6
#define FFv  2048
#define NMv  80
#define NTOK (Bv*Sv)            // 4096 tokens

// ---------------- scratch (no allocs allowed) ----------------
__device__ float g_x   [NTOK*Dv];
__device__ float g_qkv [NTOK*3*Dv];
__device__ float g_attn[NTOK*Dv];
__device__ float g_tmp [NTOK*Dv];
__device__ float g_big [NTOK*FFv];
__device__ float g_durh[NTOK*256];
__device__ float g_mels[NTOK*NMv];
__device__ float g_inv [NMv];
__device__ int   g_cum [Bv*Sv];
__device__ int   g_idx [Bv*Tv];
// transposed + hi/lo-split weights ([N,K] K-major, bf16)
__device__ __nv_bfloat16 g_qkvTH[Lv*3*Dv*Dv], g_qkvTL[Lv*3*Dv*Dv];
__device__ __nv_bfloat16 g_WoTH [Lv*Dv*Dv],   g_WoTL [Lv*Dv*Dv];
__device__ __nv_bfloat16 g_W1TH [Lv*FFv*Dv],  g_W1TL [Lv*FFv*Dv];
__device__ __nv_bfloat16 g_W2TH [Lv*Dv*FFv],  g_W2TL [Lv*Dv*FFv];
__device__ __nv_bfloat16 g_m1TH [FFv*Dv],     g_m1TL [FFv*Dv];
__device__ __nv_bfloat16 g_m2TH [NMv*FFv],    g_m2TL [NMv*FFv];
__device__ __nv_bfloat16 g_d1TH [256*Dv],     g_d1TL [256*Dv];

// ---------------- low-level helpers ----------------
__device__ __forceinline__ uint32_t smem_u32(const void* p) {
    uint32_t a;
    asm("{ .reg .u64 t; cvta.to.shared.u64 t, %1; cvt.u32.u64 %0, t; }" : "=r"(a) : "l"(p));
    return a;
}
__device__ __forceinline__ void ldsm4(uint32_t& a0, uint32_t& a1, uint32_t& a2,
                                      uint32_t& a3, uint32_t addr) {
    asm volatile("ldmatrix.sync.aligned.m8n8.x4.shared.b16 {%0,%1,%2,%3}, [%4];"
                 : "=r"(a0), "=r"(a1), "=r"(a2), "=r"(a3) : "r"(addr));
}
__device__ __forceinline__ void ldsm2(uint32_t& b0, uint32_t& b1, uint32_t addr) {
    asm volatile("ldmatrix.sync.aligned.m8n8.x2.shared.b16 {%0,%1}, [%2];"
                 : "=r"(b0), "=r"(b1) : "r"(addr));
}
__device__ __forceinline__ void mma_bf16(float* c, const uint32_t* a,
                                         uint32_t b0, uint32_t b1) {
    asm volatile("mma.sync.aligned.m16n8k16.row.col.f32.bf16.bf16.f32 "
                 "{%0,%1,%2,%3}, {%4,%5,%6,%7}, {%8,%9}, {%0,%1,%2,%3};"
                 : "+f"(c[0]), "+f"(c[1]), "+f"(c[2]), "+f"(c[3])
                 : "r"(a[0]), "r"(a[1]), "r"(a[2]), "r"(a[3]), "r"(b0), "r"(b1));
}
// split two fp32 into packed bf16x2 hi + bf16x2 lo
__device__ __forceinline__ void split2(float x, float y, uint32_t& hi, uint32_t& lo) {
    __nv_bfloat162 h = __floats2bfloat162_rn(x, y);
    float hx = __bfloat162float(__low2bfloat16(h));
    float hy = __bfloat162float(__high2bfloat16(h));
    __nv_bfloat162 l2 = __floats2bfloat162_rn(x - hx, y - hy);
    hi = *(uint32_t*)&h;
    lo = *(uint32_t*)&l2;
}

// ================= split-bf16 mma.sync GEMM =================
// C[M,N] = A[M,K] @ Bt[N,K]^T (+bias)(+relu)
// Block 128x128x32, 8 warps (warp tile 32x64). M%128==0, K%32==0. N guarded (even).
#define RSB     80u                      // smem row stride bytes (64B data + 16B pad)
#define TILE_B  (128u*RSB)               // 10240 B
#define STAGE_B (4u*TILE_B)              // A_hi, A_lo, B_hi, B_lo
#define SMEM_GEMM (2u*STAGE_B)           // 81920 B

template<int EPI>   // 0 none, 1 bias, 2 bias+relu
__global__ void __launch_bounds__(256, 1)
mgemm_k(const float* __restrict__ A,
        const __nv_bfloat16* __restrict__ BtH,
        const __nv_bfloat16* __restrict__ BtL,
        const float* __restrict__ bias, float* __restrict__ C,
        int M, int N, int K)
{
    extern __shared__ char smem[];
    uint32_t sb = smem_u32(smem);
    int tid = threadIdx.x, wid = tid >> 5, l = tid & 31;
    int m0 = blockIdx.y * 128, n0 = blockIdx.x * 128;
    int wm = (wid & 3) * 32, wn = (wid >> 2) * 64;

    float acc[2][8][4];
    #pragma unroll
    for (int mi = 0; mi < 2; mi++)
        #pragma unroll
        for (int ni = 0; ni < 8; ni++)
            #pragma unroll
            for (int q = 0; q < 4; q++) acc[mi][ni][q] = 0.f;

    int ar_ = tid >> 3, ac_ = tid & 7;    // A tile coords
    int br_ = tid >> 2, bc_ = tid & 3;    // B tile coords

    float4 ard[4];
    uint4  brh[2], brl[2];

    const int NT = K / 32;

    // ---- prefetch tile 0 ----
    {
        int k0 = 0;
        #pragma unroll
        for (int i = 0; i < 4; i++)
            ard[i] = *(const float4*)(A + (size_t)(m0 + ar_ + i * 32) * K + k0 + ac_ * 4);
        #pragma unroll
        for (int i = 0; i < 2; i++) {
            int r = br_ + i * 64;
            if (n0 + r < N) {
                brh[i] = *(const uint4*)(BtH + (size_t)(n0 + r) * K + k0 + bc_ * 8);
                brl[i] = *(const uint4*)(BtL + (size_t)(n0 + r) * K + k0 + bc_ * 8);
            } else { brh[i] = make_uint4(0,0,0,0); brl[i] = make_uint4(0,0,0,0); }
        }
    }
    // ---- store tile 0 ----
    {
        #pragma unroll
        for (int i = 0; i < 4; i++) {
            uint32_t h0, h1, l0, l1;
            split2(ard[i].x, ard[i].y, h0, l0);
            split2(ard[i].z, ard[i].w, h1, l1);
            uint32_t off = (uint32_t)(ar_ + i * 32) * RSB + ac_ * 8u;
            *(uint2*)(smem + off)          = make_uint2(h0, h1);
            *(uint2*)(smem + TILE_B + off) = make_uint2(l0, l1);
        }
        #pragma unroll
        for (int i = 0; i < 2; i++) {
            uint32_t off = (uint32_t)(br_ + i * 64) * RSB + bc_ * 16u;
            *(uint4*)(smem + 2 * TILE_B + off) = brh[i];
            *(uint4*)(smem + 3 * TILE_B + off) = brl[i];
        }
    }
    __syncthreads();

    uint32_t aoff = (uint32_t)(wm + (l & 15)) * RSB + (uint32_t)(l >> 4) * 16u;
    uint32_t boff = (uint32_t)(wn + (l & 7)) * RSB + (uint32_t)((l >> 3) & 1) * 16u;

    for (int kt = 0; kt < NT; kt++) {
        int s = kt & 1;
        // prefetch next tile into registers
        if (kt + 1 < NT) {
            int k0 = (kt + 1) * 32;
            #pragma unroll
            for (int i = 0; i < 4; i++)
                ard[i] = *(const float4*)(A + (size_t)(m0 + ar_ + i * 32) * K + k0 + ac_ * 4);
            #pragma unroll
            for (int i = 0; i < 2; i++) {
                int r = br_ + i * 64;
                if (n0 + r < N) {
                    brh[i] = *(const uint4*)(BtH + (size_t)(n0 + r) * K + k0 + bc_ * 8);
                    brl[i] = *(const uint4*)(BtL + (size_t)(n0 + r) * K + k0 + bc_ * 8);
                } else { brh[i] = make_uint4(0,0,0,0); brl[i] = make_uint4(0,0,0,0); }
            }
        }
        // compute on stage s
        {
            uint32_t aH = sb + (uint32_t)s * STAGE_B;
            uint32_t aL = aH + TILE_B;
            uint32_t bH = aH + 2 * TILE_B;
            uint32_t bL = aH + 3 * TILE_B;
            #pragma unroll
            for (int ks = 0; ks < 2; ks++) {
                uint32_t ah[2][4], al[2][4];
                #pragma unroll
                for (int mi = 0; mi < 2; mi++) {
                    uint32_t ad = aoff + (uint32_t)mi * 16u * RSB + (uint32_t)ks * 32u;
                    ldsm4(ah[mi][0], ah[mi][1], ah[mi][2], ah[mi][3], aH + ad);
                    ldsm4(al[mi][0], al[mi][1], al[mi][2], al[mi][3], aL + ad);
                }
                #pragma unroll
                for (int ni = 0; ni < 8; ni++) {
                    uint32_t bd = boff + (uint32_t)ni * 8u * RSB + (uint32_t)ks * 32u;
                    uint32_t bh0, bh1, bl0, bl1;
                    ldsm2(bh0, bh1, bH + bd);
                    ldsm2(bl0, bl1, bL + bd);
                    #pragma unroll
                    for (int mi = 0; mi < 2; mi++) {
                        mma_bf16(acc[mi][ni], ah[mi], bh0, bh1);
                        mma_bf16(acc[mi][ni], al[mi], bh0, bh1);
                        mma_bf16(acc[mi][ni], ah[mi], bl0, bl1);
                    }
                }
            }
        }
        __syncthreads();
        if (kt + 1 < NT) {
            int sn = (kt + 1) & 1;
            char* dst = smem + sn * STAGE_B;
            #pragma unroll
            for (int i = 0; i < 4; i++) {
                uint32_t h0, h1, l0, l1;
                split2(ard[i].x, ard[i].y, h0, l0);
                split2(ard[i].z, ard[i].w, h1, l1);
                uint32_t off = (uint32_t)(ar_ + i * 32) * RSB + ac_ * 8u;
                *(uint2*)(dst + off)          = make_uint2(h0, h1);
                *(uint2*)(dst + TILE_B + off) = make_uint2(l0, l1);
            }
            #pragma unroll
            for (int i = 0; i < 2; i++) {
                uint32_t off = (uint32_t)(br_ + i * 64) * RSB + bc_ * 16u;
                *(uint4*)(dst + 2 * TILE_B + off) = brh[i];
                *(uint4*)(dst + 3 * TILE_B + off) = brl[i];
            }
            __syncthreads();
        }
    }

    // epilogue
    int r_lo = l >> 2, cpair = (l & 3) * 2;
    #pragma unroll
    for (int mi = 0; mi < 2; mi++) {
        int gr0 = m0 + wm + mi * 16 + r_lo;
        #pragma unroll
        for (int ni = 0; ni < 8; ni++) {
            int gc = n0 + wn + ni * 8 + cpair;
            if (gc < N) {
                float b0 = 0.f, b1 = 0.f;
                if (EPI >= 1) { b0 = bias[gc]; b1 = bias[gc + 1]; }
                float v0 = acc[mi][ni][0] + b0, v1 = acc[mi][ni][1] + b1;
                float v2 = acc[mi][ni][2] + b0, v3 = acc[mi][ni][3] + b1;
                if (EPI == 2) {
                    v0 = fmaxf(v0, 0.f); v1 = fmaxf(v1, 0.f);
                    v2 = fmaxf(v2, 0.f); v3 = fmaxf(v3, 0.f);
                }
                *(float2*)(C + (size_t)gr0 * N + gc)       = make_float2(v0, v1);
                *(float2*)(C + (size_t)(gr0 + 8) * N + gc) = make_float2(v2, v3);
            }
        }
    }
}

// ---------------- transpose + hi/lo split: in[z][R][C] fp32 -> out[z][C][R] bf16 ----
__global__ void __launch_bounds__(256)
tsplit_k(const float* __restrict__ in, __nv_bfloat16* __restrict__ outH,
         __nv_bfloat16* __restrict__ outL, int R, int C)
{
    __shared__ float t[32][33];
    size_t zo = (size_t)blockIdx.z * R * C;
    int c0 = blockIdx.x * 32, r0 = blockIdx.y * 32;
    int x = threadIdx.x, y = threadIdx.y;
    #pragma unroll
    for (int i = 0; i < 32; i += 8) {
        int r = r0 + y + i, c = c0 + x;
        if (r < R && c < C) t[y + i][x] = in[zo + (size_t)r * C + c];
    }
    __syncthreads();
    #pragma unroll
    for (int i = 0; i < 32; i += 8) {
        int c = c0 + y + i, r = r0 + x;
        if (c < C && r < R) {
            float v = t[x][y + i];
            __nv_bfloat16 h = __float2bfloat16_rn(v);
            __nv_bfloat16 lo = __float2bfloat16_rn(v - __bfloat162float(h));
            outH[zo + (size_t)c * R + r] = h;
            outL[zo + (size_t)c * R + r] = lo;
        }
    }
}

// ---------------- misc helpers ----------------
__device__ __forceinline__ float blk_sum(float v, float* sbuf) {
    __syncthreads();
    int lane = threadIdx.x & 31, w = threadIdx.x >> 5;
    #pragma unroll
    for (int o = 16; o; o >>= 1) v += __shfl_xor_sync(0xffffffffu, v, o);
    if (lane == 0) sbuf[w] = v;
    __syncthreads();
    int nw = blockDim.x >> 5;
    float r = (threadIdx.x < nw) ? sbuf[threadIdx.x] : 0.f;
    if (w == 0) {
        #pragma unroll
        for (int o = 16; o; o >>= 1) r += __shfl_xor_sync(0xffffffffu, r, o);
        if (lane == 0) sbuf[0] = r;
    }
    __syncthreads();
    return sbuf[0];
}

// ---------------- embedding + positional encoding ----------------
__global__ void __launch_bounds__(128)
embed_k(const int* __restrict__ ids, const float* __restrict__ emb,
        const float* __restrict__ pe, float* __restrict__ x)
{
    int token = blockIdx.x;
    int tid = threadIdx.x;
    int s = token % Sv;
    int id = ids[token];
    float4 e = ((const float4*)(emb + (size_t)id * Dv))[tid];
    float4 p = ((const float4*)(pe + (size_t)s * Dv))[tid];
    e.x += p.x; e.y += p.y; e.z += p.z; e.w += p.w;
    ((float4*)(x + (size_t)token * Dv))[tid] = e;
}

// ---------------- fused attention (one block per (b,h), online softmax) ------
__global__ void __launch_bounds__(256)
attn_k(const float* __restrict__ qkv, const int* __restrict__ lens,
       float* __restrict__ o)
{
    extern __shared__ float sh[];
    float* Ks = sh;
    float* Vs = sh + Sv * DHv;
    int h = blockIdx.x, b = blockIdx.y;
    int t = threadIdx.x;

    const float* base = qkv + (size_t)b * Sv * (3 * Dv);
    const float4* krow = (const float4*)(base + (size_t)t * 3 * Dv + Dv     + h * DHv);
    const float4* vrow = (const float4*)(base + (size_t)t * 3 * Dv + 2 * Dv + h * DHv);
    float4* ksd = (float4*)(Ks + t * DHv);
    float4* vsd = (float4*)(Vs + t * DHv);
    #pragma unroll
    for (int i = 0; i < 16; i++) { ksd[i] = krow[i]; vsd[i] = vrow[i]; }
    __syncthreads();

    int len = lens[b];
    float4 q4[16];
    const float4* qrow = (const float4*)(base + (size_t)t * 3 * Dv + h * DHv);
    #pragma unroll
    for (int i = 0; i < 16; i++) q4[i] = qrow[i];

    float4 a4[16];
    #pragma unroll
    for (int i = 0; i < 16; i++) a4[i] = make_float4(0.f, 0.f, 0.f, 0.f);

    const float scale = 0.125f;
    float m = -1e30f, l = 0.f;

    for (int j = 0; j < len; j++) {
        const float4* kj = (const float4*)(Ks + j * DHv);
        float s = 0.f;
        #pragma unroll
        for (int i = 0; i < 16; i++) {
            float4 kv = kj[i];
            s += q4[i].x * kv.x + q4[i].y * kv.y + q4[i].z * kv.z + q4[i].w * kv.w;
        }
        s *= scale;
        if (s > m) {
            float corr = expf(m - s);
            l *= corr;
            #pragma unroll
            for (int i = 0; i < 16; i++) {
                a4[i].x *= corr; a4[i].y *= corr; a4[i].z *= corr; a4[i].w *= corr;
            }
            m = s;
        }
        float e = expf(s - m);
        l += e;
        const float4* vj = (const float4*)(Vs + j * DHv);
        #pragma unroll
        for (int i = 0; i < 16; i++) {
            float4 vv = vj[i];
            a4[i].x += e * vv.x; a4[i].y += e * vv.y;
            a4[i].z += e * vv.z; a4[i].w += e * vv.w;
        }
    }

    float inv = (l > 0.f) ? 1.f / l : 0.f;
    float4* orow = (float4*)(o + ((size_t)b * Sv + t) * Dv + h * DHv);
    #pragma unroll
    for (int i = 0; i < 16; i++) {
        float4 r = a4[i];
        r.x *= inv; r.y *= inv; r.z *= inv; r.w *= inv;
        orow[i] = r;
    }
}

// ---------------- residual add + LayerNorm ----------------
__global__ void __launch_bounds__(128)
add_ln_k(const float* __restrict__ x, const float* __restrict__ y,
         const float* __restrict__ s, const float* __restrict__ bta,
         float* __restrict__ out)
{
    __shared__ float sbuf[8];
    int row = blockIdx.x, tid = threadIdx.x;
    float4 v = ((const float4*)(x + (size_t)row * Dv))[tid];
    float4 w = ((const float4*)(y + (size_t)row * Dv))[tid];
    v.x += w.x; v.y += w.y; v.z += w.z; v.w += w.w;

    float sum = blk_sum(v.x + v.y + v.z + v.w, sbuf);
    float mean = sum * (1.f / Dv);
    float dx = v.x - mean, dy = v.y - mean, dz = v.z - mean, dw = v.w - mean;
    float var = blk_sum(dx*dx + dy*dy + dz*dz + dw*dw, sbuf) * (1.f / Dv);
    float rstd = rsqrtf(var + 1e-5f);

    float4 sv = ((const float4*)s)[tid];
    float4 bv = ((const float4*)bta)[tid];
    float4 r;
    r.x = dx * rstd * sv.x + bv.x;
    r.y = dy * rstd * sv.y + bv.y;
    r.z = dz * rstd * sv.z + bv.z;
    r.w = dw * rstd * sv.w + bv.w;
    ((float4*)(out + (size_t)row * Dv))[tid] = r;
}

// ---------------- duration head ----------------
__global__ void __launch_bounds__(256)
dur_head_k(const float* __restrict__ durh, const float* __restrict__ W2,
           const float* __restrict__ b2, float* __restrict__ dur)
{
    __shared__ float sbuf[8];
    int row = blockIdx.x, tid = threadIdx.x;
    float v = durh[(size_t)row * 256 + tid] * W2[tid];
    v = blk_sum(v, sbuf);
    if (tid == 0) {
        float z = v + b2[0];
        dur[row] = (z > 20.f) ? z : log1pf(expf(z));
    }
}

// ---------------- cumulative durations ----------------
__global__ void cumsum_k(const float* __restrict__ dur, int* __restrict__ cum)
{
    int b = blockIdx.x;
    if (threadIdx.x == 0) {
        int c = 0;
        for (int s2 = 0; s2 < Sv; s2++) {
            int d = (int)rintf(dur[b * Sv + s2]);
            if (d < 1) d = 1;
            c += d;
            cum[b * Sv + s2] = c;
        }
    }
}

// ---------------- frame -> source index ----------------
__global__ void __launch_bounds__(256)
idx_k(const int* __restrict__ cum, int* __restrict__ idx)
{
    int b = blockIdx.y;
    int t = blockIdx.x * 256 + threadIdx.x;
    const int* c = cum + b * Sv;
    int total = c[Sv - 1];
    int lo = 0, hi = Sv;
    while (lo < hi) { int mid = (lo + hi) >> 1; if (c[mid] <= t) lo = mid + 1; else hi = mid; }
    int ix = lo > (Sv - 1) ? (Sv - 1) : lo;
    idx[b * Tv + t] = (t < total) ? ix : -1;
}

// ---------------- mel for invalid frames ----------------
__global__ void __launch_bounds__(256)
melinv_k(const float* __restrict__ b1, const float* __restrict__ W2,
         const float* __restrict__ b2, float* __restrict__ inv)
{
    __shared__ float sbuf[8];
    int nm = blockIdx.x, tid = threadIdx.x;
    float v = 0.f;
    for (int f = tid; f < FFv; f += 256) {
        float r = b1[f]; r = r > 0.f ? r : 0.f;
        v += r * W2[(size_t)f * NMv + nm];
    }
    v = blk_sum(v, sbuf);
    if (tid == 0) inv[nm] = v + b2[nm];
}

// ---------------- gather mel rows into [B, NM, T] ----------------
__global__ void __launch_bounds__(256)
gather_k(const int* __restrict__ idx, const float* __restrict__ mels,
         const float* __restrict__ inv, float* __restrict__ mel)
{
    int t = blockIdx.x * 256 + threadIdx.x;
    int bn = blockIdx.y;
    int b = bn / NMv, nm = bn % NMv;
    int iv = idx[b * Tv + t];
    mel[(size_t)bn * Tv + t] =
        (iv < 0) ? inv[nm] : mels[((size_t)b * Sv + iv) * NMv + nm];
}

// ---------------- host launcher ----------------
extern "C" void kernel_launch(void* const* d_in, const int* in_sizes, int n_in,
                              void* d_out, int out_size)
{
    const int*   ids    = (const int*)  d_in[0];
    const int*   lens   = (const int*)  d_in[1];
    const float* emb    = (const float*)d_in[3];
    const float* pe     = (const float*)d_in[4];
    const float* Wqkv   = (const float*)d_in[5];
    const float* bqkv   = (const float*)d_in[6];
    const float* Wo     = (const float*)d_in[7];
    const float* bo     = (const float*)d_in[8];
    const float* ln1s   = (const float*)d_in[9];
    const float* ln1b   = (const float*)d_in[10];
    const float* ln2s   = (const float*)d_in[11];
    const float* ln2b   = (const float*)d_in[12];
    const float* W1     = (const float*)d_in[13];
    const float* b1     = (const float*)d_in[14];
    const float* W2     = (const float*)d_in[15];
    const float* b2     = (const float*)d_in[16];
    const float* melW1  = (const float*)d_in[17];
    const float* melb1  = (const float*)d_in[18];
    const float* melW2  = (const float*)d_in[19];
    const float* melb2  = (const float*)d_in[20];
    const float* durW1  = (const float*)d_in[21];
    const float* durb1  = (const float*)d_in[22];
    const float* durW2  = (const float*)d_in[23];
    const float* durb2  = (const float*)d_in[24];

    float* out     = (float*)d_out;
    float* out_mel = out;
    float* out_dur = out + (size_t)Bv * NMv * Tv;
    float* out_enc = out_dur + (size_t)Bv * Sv;

    float *x, *qkv, *attn, *tmp, *big, *durh, *mels, *inv;
    int *cum, *idxp;
    __nv_bfloat16 *qkvTH, *qkvTL, *WoTH, *WoTL, *W1TH, *W1TL, *W2TH, *W2TL;
    __nv_bfloat16 *m1TH, *m1TL, *m2TH, *m2TL, *d1TH, *d1TL;
    cudaGetSymbolAddress((void**)&x,     g_x);
    cudaGetSymbolAddress((void**)&qkv,   g_qkv);
    cudaGetSymbolAddress((void**)&attn,  g_attn);
    cudaGetSymbolAddress((void**)&tmp,   g_tmp);
    cudaGetSymbolAddress((void**)&big,   g_big);
    cudaGetSymbolAddress((void**)&durh,  g_durh);
    cudaGetSymbolAddress((void**)&mels,  g_mels);
    cudaGetSymbolAddress((void**)&inv,   g_inv);
    cudaGetSymbolAddress((void**)&cum,   g_cum);
    cudaGetSymbolAddress((void**)&idxp,  g_idx);
    cudaGetSymbolAddress((void**)&qkvTH, g_qkvTH);
    cudaGetSymbolAddress((void**)&qkvTL, g_qkvTL);
    cudaGetSymbolAddress((void**)&WoTH,  g_WoTH);
    cudaGetSymbolAddress((void**)&WoTL,  g_WoTL);
    cudaGetSymbolAddress((void**)&W1TH,  g_W1TH);
    cudaGetSymbolAddress((void**)&W1TL,  g_W1TL);
    cudaGetSymbolAddress((void**)&W2TH,  g_W2TH);
    cudaGetSymbolAddress((void**)&W2TL,  g_W2TL);
    cudaGetSymbolAddress((void**)&m1TH,  g_m1TH);
    cudaGetSymbolAddress((void**)&m1TL,  g_m1TL);
    cudaGetSymbolAddress((void**)&m2TH,  g_m2TH);
    cudaGetSymbolAddress((void**)&m2TL,  g_m2TL);
    cudaGetSymbolAddress((void**)&d1TH,  g_d1TH);
    cudaGetSymbolAddress((void**)&d1TL,  g_d1TL);

    const int attn_smem = 2 * Sv * DHv * (int)sizeof(float);
    cudaFuncSetAttribute(attn_k, cudaFuncAttributeMaxDynamicSharedMemorySize, attn_smem);
    cudaFuncSetAttribute(mgemm_k<1>, cudaFuncAttributeMaxDynamicSharedMemorySize, SMEM_GEMM);
    cudaFuncSetAttribute(mgemm_k<2>, cudaFuncAttributeMaxDynamicSharedMemorySize, SMEM_GEMM);

    dim3 tb(32, 8);
    tsplit_k<<<dim3(48, 16, Lv), tb>>>(Wqkv,  qkvTH, qkvTL, Dv, 3 * Dv);
    tsplit_k<<<dim3(16, 16, Lv), tb>>>(Wo,    WoTH,  WoTL,  Dv, Dv);
    tsplit_k<<<dim3(64, 16, Lv), tb>>>(W1,    W1TH,  W1TL,  Dv, FFv);
    tsplit_k<<<dim3(16, 64, Lv), tb>>>(W2,    W2TH,  W2TL,  FFv, Dv);
    tsplit_k<<<dim3(64, 16, 1),  tb>>>(melW1, m1TH,  m1TL,  Dv, FFv);
    tsplit_k<<<dim3(3,  64, 1),  tb>>>(melW2, m2TH,  m2TL,  FFv, NMv);
    tsplit_k<<<dim3(8,  16, 1),  tb>>>(durW1, d1TH,  d1TL,  Dv, 256);

    embed_k<<<NTOK, 128>>>(ids, emb, pe, x);

    for (int l = 0; l < Lv; l++) {
        mgemm_k<1><<<dim3(12, 32), 256, SMEM_GEMM>>>(
            x, qkvTH + (size_t)l * 3 * Dv * Dv, qkvTL + (size_t)l * 3 * Dv * Dv,
            bqkv + l * 3 * Dv, qkv, NTOK, 3 * Dv, Dv);
        attn_k<<<dim3(Hv, Bv), 256, attn_smem>>>(qkv, lens, attn);
        mgemm_k<1><<<dim3(4, 32), 256, SMEM_GEMM>>>(
            attn, WoTH + (size_t)l * Dv * Dv, WoTL + (size_t)l * Dv * Dv,
            bo + l * Dv, tmp, NTOK, Dv, Dv);
        add_ln_k<<<NTOK, 128>>>(x, tmp, ln1s + l * Dv, ln1b + l * Dv, x);
        mgemm_k<2><<<dim3(16, 32), 256, SMEM_GEMM>>>(
            x, W1TH + (size_t)l * FFv * Dv, W1TL + (size_t)l * FFv * Dv,
            b1 + l * FFv, big, NTOK, FFv, Dv);
        mgemm_k<1><<<dim3(4, 32), 256, SMEM_GEMM>>>(
            big, W2TH + (size_t)l * Dv * FFv, W2TL + (size_t)l * Dv * FFv,
            b2 + l * Dv, tmp, NTOK, Dv, FFv);
        add_ln_k<<<NTOK, 128>>>(x, tmp, ln2s + l * Dv, ln2b + l * Dv, x);
    }

    cudaMemcpyAsync(out_enc, x, (size_t)NTOK * Dv * sizeof(float),
                    cudaMemcpyDeviceToDevice);

    // duration head
    mgemm_k<2><<<dim3(2, 32), 256, SMEM_GEMM>>>(x, d1TH, d1TL, durb1, durh,
                                                NTOK, 256, Dv);
    dur_head_k<<<NTOK, 256>>>(durh, durW2, durb2, out_dur);
    cumsum_k<<<Bv, 32>>>(out_dur, cum);

    // mel head on source tokens (gather commutes with row-wise MLP)
    mgemm_k<2><<<dim3(16, 32), 256, SMEM_GEMM>>>(x, m1TH, m1TL, melb1, big,
                                                 NTOK, FFv, Dv);
    mgemm_k<1><<<dim3(1, 32), 256, SMEM_GEMM>>>(big, m2TH, m2TL, melb2, mels,
                                                NTOK, NMv, FFv);
    melinv_k<<<NMv, 256>>>(melb1, melW2, melb2, inv);

    idx_k<<<dim3(Tv / 256, Bv), 256>>>(cum, idxp);
    gather_k<<<dim3(Tv / 256, Bv * NMv), 256>>>(idxp, mels, inv, out_mel);
}